// round 2
// baseline (speedup 1.0000x reference)
#include <cuda_runtime.h>
#include <cstdint>

// Problem constants
#define T_TOK 8192
#define D_DIM 768
#define E_EXP 8
#define F_DIM 3072

// ---------------- device scratch (no allocations allowed) ----------------
__device__ int g_idx[T_TOK];
__device__ int g_cnt[E_EXP];
__device__ int g_off[E_EXP + 1];
__device__ int g_cur[E_EXP];
__device__ int g_perm[T_TOK];
__device__ float g_H[(size_t)T_TOK * F_DIM];   // 100 MB intermediate (grouped rows)

// ---------------- helpers ----------------
__device__ __forceinline__ uint32_t f2tf32(float v) {
    uint32_t r;
    asm("cvt.rna.tf32.f32 %0, %1;" : "=r"(r) : "f"(v));
    return r;
}

__device__ __forceinline__ float gelu_exact(float v) {
    return 0.5f * v * (1.0f + erff(v * 0.70710678118654752f));
}

// ---------------- small kernels: routing ----------------
__global__ void zero_kernel() {
    int t = threadIdx.x;
    if (t < E_EXP) { g_cnt[t] = 0; g_cur[t] = 0; }
}

// one warp per token: logits = x[t] @ gate_w + gate_b ; argmax (softmax is monotone)
__global__ void gate_kernel(const float* __restrict__ x,
                            const float* __restrict__ gw,
                            const float* __restrict__ gb) {
    int t = blockIdx.x * 8 + (threadIdx.x >> 5);
    int lane = threadIdx.x & 31;
    const float* xr = x + (size_t)t * D_DIM;
    float acc[8] = {0.f,0.f,0.f,0.f,0.f,0.f,0.f,0.f};
    for (int j = lane; j < D_DIM; j += 32) {
        float xv = xr[j];
        const float4* g4 = reinterpret_cast<const float4*>(gw + (size_t)j * 8);
        float4 a = g4[0], b = g4[1];
        acc[0] += xv * a.x; acc[1] += xv * a.y; acc[2] += xv * a.z; acc[3] += xv * a.w;
        acc[4] += xv * b.x; acc[5] += xv * b.y; acc[6] += xv * b.z; acc[7] += xv * b.w;
    }
#pragma unroll
    for (int o = 16; o; o >>= 1)
#pragma unroll
        for (int e = 0; e < 8; e++)
            acc[e] += __shfl_xor_sync(0xffffffffu, acc[e], o);
    if (lane == 0) {
        int best = 0;
        float bv = acc[0] + gb[0];
#pragma unroll
        for (int e = 1; e < 8; e++) {
            float v = acc[e] + gb[e];
            if (v > bv) { bv = v; best = e; }
        }
        g_idx[t] = best;
        atomicAdd(&g_cnt[best], 1);
    }
}

__global__ void offset_kernel() {
    if (threadIdx.x == 0) {
        int s = 0;
        for (int i = 0; i < E_EXP; i++) { g_off[i] = s; s += g_cnt[i]; }
        g_off[E_EXP] = s;
    }
}

__global__ void scatter_kernel() {
    int t = blockIdx.x * 256 + threadIdx.x;
    int e = g_idx[t];
    int p = atomicAdd(&g_cur[e], 1);
    g_perm[g_off[e] + p] = t;
}

// ---------------- grouped GEMM (tf32 mma.sync, 128x128x32 tiles) ----------------
// GEMM1: H[g] = gelu( gather(x)[g] @ w1[e] + b1[e] )   (GATHER_A, DO_GELU, C -> g_H grouped)
// GEMM2: out[tok] = H[g] @ w2[e] + b2[e]               (A = g_H grouped, SCATTER_C via perm)
template<int K, int N, bool GATHER_A, bool DO_GELU, bool SCATTER_C>
__global__ void moe_gemm(const float* __restrict__ Ax,
                         const float* __restrict__ W,
                         const float* __restrict__ Bias,
                         float* __restrict__ Cx) {
    __shared__ uint32_t As[128][36];   // [m][k], stride 36 -> conflict-free frag loads
    __shared__ uint32_t Bs[32][136];   // [k][n], stride 136 -> conflict-free frag loads
    __shared__ int sP[128];
    __shared__ int sOff[E_EXP + 1];

    int tid = threadIdx.x;
    if (tid <= E_EXP) sOff[tid] = g_off[tid];
    __syncthreads();

    // map blockIdx.y -> (expert, local m-tile)
    int rt = blockIdx.y;
    int e = -1, mt = 0;
    {
        int base = 0;
#pragma unroll
        for (int i = 0; i < E_EXP; i++) {
            int c = sOff[i + 1] - sOff[i];
            int tl = (c + 127) >> 7;
            if (e < 0 && rt < base + tl) { e = i; mt = rt - base; }
            base += tl;
        }
    }
    if (e < 0) return;   // padded tile, nothing to do

    int cnt   = sOff[e + 1] - sOff[e];
    int m0    = mt << 7;
    int rows  = min(128, cnt - m0);
    int grow0 = sOff[e] + m0;           // grouped row base
    int n0    = blockIdx.x << 7;

    if (tid < 128) sP[tid] = (tid < rows) ? g_perm[grow0 + tid] : -1;
    __syncthreads();

    const float* A  = GATHER_A ? Ax : (const float*)g_H;
    const float* We = W + (size_t)e * K * N;

    float acc[2][8][4];
#pragma unroll
    for (int im = 0; im < 2; im++)
#pragma unroll
        for (int jn = 0; jn < 8; jn++)
#pragma unroll
            for (int q = 0; q < 4; q++) acc[im][jn][q] = 0.f;

    int wid = tid >> 5, lane = tid & 31;
    int wm = wid & 3, wn = wid >> 2;   // warp tile: 32 rows x 64 cols
    int lr = lane >> 2, lc = lane & 3;

    for (int kt = 0; kt < K; kt += 32) {
        // A tile 128x32 (float4 per thread x4)
#pragma unroll
        for (int i = 0; i < 4; i++) {
            int idx = tid + i * 256;
            int row = idx >> 3;
            int c4  = (idx & 7) << 2;
            float4 v = make_float4(0.f, 0.f, 0.f, 0.f);
            if (GATHER_A) {
                int sr = sP[row];
                if (sr >= 0)
                    v = *reinterpret_cast<const float4*>(A + (size_t)sr * K + kt + c4);
            } else {
                if (row < rows)
                    v = *reinterpret_cast<const float4*>(A + (size_t)(grow0 + row) * K + kt + c4);
            }
            As[row][c4 + 0] = f2tf32(v.x);
            As[row][c4 + 1] = f2tf32(v.y);
            As[row][c4 + 2] = f2tf32(v.z);
            As[row][c4 + 3] = f2tf32(v.w);
        }
        // B tile 32x128
#pragma unroll
        for (int i = 0; i < 4; i++) {
            int idx = tid + i * 256;
            int row = idx >> 5;
            int c4  = (idx & 31) << 2;
            float4 v = *reinterpret_cast<const float4*>(We + (size_t)(kt + row) * N + n0 + c4);
            Bs[row][c4 + 0] = f2tf32(v.x);
            Bs[row][c4 + 1] = f2tf32(v.y);
            Bs[row][c4 + 2] = f2tf32(v.z);
            Bs[row][c4 + 3] = f2tf32(v.w);
        }
        __syncthreads();

#pragma unroll
        for (int ks = 0; ks < 4; ks++) {
            uint32_t a[2][4], b[8][2];
#pragma unroll
            for (int im = 0; im < 2; im++) {
                int r = wm * 32 + im * 16 + lr;
                int k = ks * 8 + lc;
                a[im][0] = As[r][k];
                a[im][1] = As[r + 8][k];
                a[im][2] = As[r][k + 4];
                a[im][3] = As[r + 8][k + 4];
            }
#pragma unroll
            for (int jn = 0; jn < 8; jn++) {
                int n = wn * 64 + jn * 8 + lr;
                int k = ks * 8 + lc;
                b[jn][0] = Bs[k][n];
                b[jn][1] = Bs[k + 4][n];
            }
#pragma unroll
            for (int im = 0; im < 2; im++)
#pragma unroll
                for (int jn = 0; jn < 8; jn++) {
                    asm volatile(
                        "mma.sync.aligned.m16n8k8.row.col.f32.tf32.tf32.f32 "
                        "{%0,%1,%2,%3}, {%4,%5,%6,%7}, {%8,%9}, {%0,%1,%2,%3};\n"
                        : "+f"(acc[im][jn][0]), "+f"(acc[im][jn][1]),
                          "+f"(acc[im][jn][2]), "+f"(acc[im][jn][3])
                        : "r"(a[im][0]), "r"(a[im][1]), "r"(a[im][2]), "r"(a[im][3]),
                          "r"(b[jn][0]), "r"(b[jn][1]));
                }
        }
        __syncthreads();
    }

    // epilogue
    const float* be = Bias + (size_t)e * N + n0;
#pragma unroll
    for (int im = 0; im < 2; im++) {
#pragma unroll
        for (int half = 0; half < 2; half++) {
            int r = wm * 32 + im * 16 + lr + half * 8;
            bool rvalid = (r < rows);
            int tok = -1;
            if (SCATTER_C && rvalid) tok = sP[r];
#pragma unroll
            for (int jn = 0; jn < 8; jn++) {
                int col = wn * 64 + jn * 8 + lc * 2;
                float v0 = acc[im][jn][half * 2 + 0] + be[col];
                float v1 = acc[im][jn][half * 2 + 1] + be[col + 1];
                if (DO_GELU) { v0 = gelu_exact(v0); v1 = gelu_exact(v1); }
                if (rvalid) {
                    if (SCATTER_C) {
                        float2* dst = reinterpret_cast<float2*>(
                            Cx + (size_t)tok * N + n0 + col);
                        *dst = make_float2(v0, v1);
                    } else {
                        float2* dst = reinterpret_cast<float2*>(
                            g_H + (size_t)(grow0 + r) * N + n0 + col);
                        *dst = make_float2(v0, v1);
                    }
                }
            }
        }
    }
}

// ---------------- launch ----------------
extern "C" void kernel_launch(void* const* d_in, const int* in_sizes, int n_in,
                              void* d_out, int out_size) {
    const float* x  = (const float*)d_in[0];
    const float* gw = (const float*)d_in[1];
    const float* gb = (const float*)d_in[2];
    const float* w1 = (const float*)d_in[3];
    const float* b1 = (const float*)d_in[4];
    const float* w2 = (const float*)d_in[5];
    const float* b2 = (const float*)d_in[6];
    float* out = (float*)d_out;

    zero_kernel<<<1, 32>>>();
    gate_kernel<<<T_TOK / 8, 256>>>(x, gw, gb);
    offset_kernel<<<1, 1>>>();
    scatter_kernel<<<T_TOK / 256, 256>>>();

    // max row tiles across experts: sum ceil(cnt_e/128) <= 64 + 8 = 72
    moe_gemm<D_DIM, F_DIM, true,  true,  false><<<dim3(F_DIM / 128, 72), 256>>>(x, w1, b1, nullptr);
    moe_gemm<F_DIM, D_DIM, false, false, true ><<<dim3(D_DIM / 128, 72), 256>>>(nullptr, w2, b2, out);
}

// round 8
// speedup vs baseline: 1.4050x; 1.4050x over previous
#include <cuda_runtime.h>
#include <cstdint>

// Problem constants
#define T_TOK 8192
#define D_DIM 768
#define E_EXP 8
#define F_DIM 3072

// ---------------- device scratch (no allocations allowed) ----------------
__device__ int g_idx[T_TOK];
__device__ int g_cnt[E_EXP];
__device__ int g_off[E_EXP + 1];
__device__ int g_cur[E_EXP];
__device__ int g_perm[T_TOK];
__device__ float g_H[(size_t)T_TOK * F_DIM];   // grouped intermediate rows

// ---------------- helpers ----------------
__device__ __forceinline__ uint32_t f2tf32(float v) {
    uint32_t r;
    asm("cvt.rna.tf32.f32 %0, %1;" : "=r"(r) : "f"(v));
    return r;
}

__device__ __forceinline__ float gelu_exact(float v) {
    return 0.5f * v * (1.0f + erff(v * 0.70710678118654752f));
}

__device__ __forceinline__ uint32_t smem_u32(const void* p) {
    uint32_t a;
    asm("{ .reg .u64 t; cvta.to.shared.u64 t, %1; cvt.u32.u64 %0, t; }"
        : "=r"(a) : "l"(p));
    return a;
}

__device__ __forceinline__ void cp_async16(uint32_t dst, const void* src) {
    asm volatile("cp.async.cg.shared.global [%0], [%1], 16;"
                 :: "r"(dst), "l"(src) : "memory");
}
#define CP_COMMIT()  asm volatile("cp.async.commit_group;" ::: "memory")
#define CP_WAIT1()   asm volatile("cp.async.wait_group 1;" ::: "memory")

// ---------------- small kernels: routing ----------------
__global__ void zero_kernel() {
    int t = threadIdx.x;
    if (t < E_EXP) { g_cnt[t] = 0; g_cur[t] = 0; }
}

__global__ void gate_kernel(const float* __restrict__ x,
                            const float* __restrict__ gw,
                            const float* __restrict__ gb) {
    int t = blockIdx.x * 8 + (threadIdx.x >> 5);
    int lane = threadIdx.x & 31;
    const float* xr = x + (size_t)t * D_DIM;
    float acc[8] = {0.f,0.f,0.f,0.f,0.f,0.f,0.f,0.f};
    for (int j = lane; j < D_DIM; j += 32) {
        float xv = xr[j];
        const float4* g4 = reinterpret_cast<const float4*>(gw + (size_t)j * 8);
        float4 a = g4[0], b = g4[1];
        acc[0] += xv * a.x; acc[1] += xv * a.y; acc[2] += xv * a.z; acc[3] += xv * a.w;
        acc[4] += xv * b.x; acc[5] += xv * b.y; acc[6] += xv * b.z; acc[7] += xv * b.w;
    }
#pragma unroll
    for (int o = 16; o; o >>= 1)
#pragma unroll
        for (int e = 0; e < 8; e++)
            acc[e] += __shfl_xor_sync(0xffffffffu, acc[e], o);
    if (lane == 0) {
        int best = 0;
        float bv = acc[0] + gb[0];
#pragma unroll
        for (int e = 1; e < 8; e++) {
            float v = acc[e] + gb[e];
            if (v > bv) { bv = v; best = e; }
        }
        g_idx[t] = best;
        atomicAdd(&g_cnt[best], 1);
    }
}

__global__ void offset_kernel() {
    if (threadIdx.x == 0) {
        int s = 0;
        for (int i = 0; i < E_EXP; i++) { g_off[i] = s; s += g_cnt[i]; }
        g_off[E_EXP] = s;
    }
}

__global__ void scatter_kernel() {
    int t = blockIdx.x * 256 + threadIdx.x;
    int e = g_idx[t];
    int p = atomicAdd(&g_cur[e], 1);
    g_perm[g_off[e] + p] = t;
}

// ---------------- grouped GEMM, tf32 mma.sync, cp.async 2-stage pipeline ----
// dynamic smem layout (floats):
//   stage s (s=0,1) at s*8960:
//     A: 128 rows x stride 36  (4608 floats)   raw f32
//     B: 32 rows  x stride 136 (4352 floats)   raw f32, at +4608
//   sP: int[128] at float-offset 17920
#define STG_F   8960
#define A_STRIDE 36
#define B_STRIDE 136
#define B_BASE  4608
#define SP_OFF  17920
#define SMEM_BYTES 73728

template<int K, int N, bool GATHER_A, bool DO_GELU, bool SCATTER_C>
__global__ void __launch_bounds__(256)
moe_gemm(const float* __restrict__ Ax,
         const float* __restrict__ W,
         const float* __restrict__ Bias,
         float* __restrict__ Cx) {
    extern __shared__ float smf[];
    uint32_t sb = smem_u32(smf);
    int tid = threadIdx.x;

    // map blockIdx.y -> (expert, local m-tile)
    int rt = blockIdx.y;
    int e = -1, mt = 0;
    {
        int base = 0;
#pragma unroll
        for (int i = 0; i < E_EXP; i++) {
            int c = g_off[i + 1] - g_off[i];
            int tl = (c + 127) >> 7;
            if (e < 0 && rt < base + tl) { e = i; mt = rt - base; }
            base += tl;
        }
    }
    if (e < 0) return;

    int cnt   = g_off[e + 1] - g_off[e];
    int m0    = mt << 7;
    int rows  = min(128, cnt - m0);
    int grow0 = g_off[e] + m0;
    int n0    = blockIdx.x << 7;

    int* sP = reinterpret_cast<int*>(smf + SP_OFF);
    if (tid < 128) sP[tid] = (tid < rows) ? g_perm[grow0 + tid] : -1;
    __syncthreads();

    const float* A  = GATHER_A ? Ax : (const float*)g_H;
    const float* We = W + (size_t)e * K * N;

    // per-thread cp.async coordinates
    int a_row = tid >> 3;                 // base row; +i*32 for i=0..3 -> 128 rows
    int a_c4  = (tid & 7) << 2;           // f32 col of 16B chunk (0,4,..,28)
    int b_row = tid >> 5;                 // +i*8 -> 32 rows
    int b_c4  = (tid & 31) << 2;          // f32 col (0,4,..,124)

    // A source row pointers (fixed across k-tiles): 4 rows per thread.
    // Invalid/padded rows CLAMP to a valid row (tile has >=1 valid row);
    // their accumulators hold garbage but are never stored (rvalid mask).
    const float* a_src[4];
#pragma unroll
    for (int i = 0; i < 4; i++) {
        int r = a_row + i * 32;
        if (GATHER_A) {
            int sr = sP[r];
            if (sr < 0) sr = sP[0];
            a_src[i] = A + (size_t)sr * K;
        } else {
            int rr = (r < rows) ? (grow0 + r) : grow0;
            a_src[i] = A + (size_t)rr * K;
        }
    }

    const int NK = K / 32;

    // issue loads for k-tile kt into stage s
    auto issue = [&](int s, int kt) {
        int kbase = kt << 5;
        uint32_t stg = sb + (uint32_t)(s * STG_F * 4);
        // A: 128x32 -> 4 chunks per thread
#pragma unroll
        for (int i = 0; i < 4; i++) {
            int r = a_row + i * 32;
            cp_async16(stg + (uint32_t)((r * A_STRIDE + a_c4) * 4),
                       a_src[i] + kbase + a_c4);
        }
        // B: 32x128 -> 4 chunks per thread
#pragma unroll
        for (int i = 0; i < 4; i++) {
            int r = b_row + i * 8;
            cp_async16(stg + (uint32_t)(B_BASE * 4 + (r * B_STRIDE + b_c4) * 4),
                       We + (size_t)(kbase + r) * N + n0 + b_c4);
        }
    };

    float acc[2][8][4];
#pragma unroll
    for (int im = 0; im < 2; im++)
#pragma unroll
        for (int jn = 0; jn < 8; jn++)
#pragma unroll
            for (int q = 0; q < 4; q++) acc[im][jn][q] = 0.f;

    int wid = tid >> 5, lane = tid & 31;
    int wm = wid & 3, wn = wid >> 2;      // warp tile: 32 rows x 64 cols
    int lr = lane >> 2, lc = lane & 3;

    // prologue: fill both stages
    issue(0, 0); CP_COMMIT();
    issue(1, 1); CP_COMMIT();

    for (int kt = 0; kt < NK; kt++) {
        int s = kt & 1;
        const float* As = smf + s * STG_F;
        const float* Bs = As + B_BASE;

        CP_WAIT1();
        __syncthreads();

#pragma unroll
        for (int ks = 0; ks < 4; ks++) {
            uint32_t a[2][4], b[8][2];
#pragma unroll
            for (int im = 0; im < 2; im++) {
                int r = wm * 32 + im * 16 + lr;
                int k = ks * 8 + lc;
                a[im][0] = f2tf32(As[r * A_STRIDE + k]);
                a[im][1] = f2tf32(As[(r + 8) * A_STRIDE + k]);
                a[im][2] = f2tf32(As[r * A_STRIDE + k + 4]);
                a[im][3] = f2tf32(As[(r + 8) * A_STRIDE + k + 4]);
            }
#pragma unroll
            for (int jn = 0; jn < 8; jn++) {
                int n = wn * 64 + jn * 8 + lr;
                int k = ks * 8 + lc;
                b[jn][0] = f2tf32(Bs[k * B_STRIDE + n]);
                b[jn][1] = f2tf32(Bs[(k + 4) * B_STRIDE + n]);
            }
#pragma unroll
            for (int im = 0; im < 2; im++)
#pragma unroll
                for (int jn = 0; jn < 8; jn++) {
                    asm volatile(
                        "mma.sync.aligned.m16n8k8.row.col.f32.tf32.tf32.f32 "
                        "{%0,%1,%2,%3}, {%4,%5,%6,%7}, {%8,%9}, {%0,%1,%2,%3};\n"
                        : "+f"(acc[im][jn][0]), "+f"(acc[im][jn][1]),
                          "+f"(acc[im][jn][2]), "+f"(acc[im][jn][3])
                        : "r"(a[im][0]), "r"(a[im][1]), "r"(a[im][2]), "r"(a[im][3]),
                          "r"(b[jn][0]), "r"(b[jn][1]));
                }
        }
        __syncthreads();

        if (kt + 2 < NK) issue(s, kt + 2);
        CP_COMMIT();
    }

    // epilogue
    const float* be = Bias + (size_t)e * N + n0;
#pragma unroll
    for (int im = 0; im < 2; im++) {
#pragma unroll
        for (int half = 0; half < 2; half++) {
            int r = wm * 32 + im * 16 + lr + half * 8;
            bool rvalid = (r < rows);
            int tok = -1;
            if (SCATTER_C && rvalid) tok = sP[r];
#pragma unroll
            for (int jn = 0; jn < 8; jn++) {
                int col = wn * 64 + jn * 8 + lc * 2;
                float v0 = acc[im][jn][half * 2 + 0] + be[col];
                float v1 = acc[im][jn][half * 2 + 1] + be[col + 1];
                if (DO_GELU) { v0 = gelu_exact(v0); v1 = gelu_exact(v1); }
                if (rvalid) {
                    if (SCATTER_C) {
                        float2* dst = reinterpret_cast<float2*>(
                            Cx + (size_t)tok * N + n0 + col);
                        *dst = make_float2(v0, v1);
                    } else {
                        float2* dst = reinterpret_cast<float2*>(
                            g_H + (size_t)(grow0 + r) * N + n0 + col);
                        *dst = make_float2(v0, v1);
                    }
                }
            }
        }
    }
}

// ---------------- launch ----------------
extern "C" void kernel_launch(void* const* d_in, const int* in_sizes, int n_in,
                              void* d_out, int out_size) {
    const float* x  = (const float*)d_in[0];
    const float* gw = (const float*)d_in[1];
    const float* gb = (const float*)d_in[2];
    const float* w1 = (const float*)d_in[3];
    const float* b1 = (const float*)d_in[4];
    const float* w2 = (const float*)d_in[5];
    const float* b2 = (const float*)d_in[6];
    float* out = (float*)d_out;

    cudaFuncSetAttribute(moe_gemm<D_DIM, F_DIM, true,  true,  false>,
                         cudaFuncAttributeMaxDynamicSharedMemorySize, SMEM_BYTES);
    cudaFuncSetAttribute(moe_gemm<F_DIM, D_DIM, false, false, true>,
                         cudaFuncAttributeMaxDynamicSharedMemorySize, SMEM_BYTES);

    zero_kernel<<<1, 32>>>();
    gate_kernel<<<T_TOK / 8, 256>>>(x, gw, gb);
    offset_kernel<<<1, 1>>>();
    scatter_kernel<<<T_TOK / 256, 256>>>();

    // max row tiles across experts: floor(8192/128) + 8 = 72
    moe_gemm<D_DIM, F_DIM, true,  true,  false>
        <<<dim3(F_DIM / 128, 72), 256, SMEM_BYTES>>>(x, w1, b1, nullptr);
    moe_gemm<F_DIM, D_DIM, false, false, true>
        <<<dim3(D_DIM / 128, 72), 256, SMEM_BYTES>>>(nullptr, w2, b2, out);
}